// round 4
// baseline (speedup 1.0000x reference)
#include <cuda_runtime.h>

#define N_IN   163842
#define N_OUT  40962
#define NBLK   321          // ceil(40962/128)

// ---------------- scratch (device globals; no allocation) ----------------
__device__ __align__(256) float g_pooled[N_OUT * 64];
__device__ __align__(256) float g_raw[N_OUT * 128];
__device__ __align__(256) float g_h1[N_OUT * 128];
__device__ __align__(256) float g_part[2 * 128 * NBLK];
__device__ __align__(256) float g_coef[256];

// ---------------- 1-ring mean pool with the reference's reshape ----------
// pooled[n,f] = (1/7) * sum_{j=0..6} flat[f*7+j] where flat[q] = x[po[n*7+q/64]][q%64]
__global__ void pool_kernel(const float* __restrict__ x, const int* __restrict__ po) {
    __shared__ float sh[8 * 448];
    int nb0 = blockIdx.x * 8;
    int tid = threadIdx.x;
    for (int e = tid; e < 8 * 448; e += 256) {
        int ln = e / 448;
        int q  = e - ln * 448;
        int node = nb0 + ln;
        if (node < N_OUT) {
            int r = q >> 6, c = q & 63;
            int srow = po[node * 7 + r];
            sh[e] = x[(size_t)srow * 64 + c];
        }
    }
    __syncthreads();
    for (int e = tid; e < 8 * 64; e += 256) {
        int ln = e >> 6, f = e & 63;
        int node = nb0 + ln;
        if (node < N_OUT) {
            const float* p = &sh[ln * 448 + f * 7];
            float s = p[0] + p[1] + p[2] + p[3] + p[4] + p[5] + p[6];
            g_pooled[node * 64 + f] = s * (1.0f / 7.0f);
        }
    }
}

// ---------------- gather-GEMM: (M x 7C) @ (7C x 128) + bias --------------
// Fuses per-block BN sum/sumsq partials (deterministic tree reduce, no atomics).
template <int C>
__global__ void __launch_bounds__(256) conv_kernel(
    const float* __restrict__ src,
    const int* __restrict__ neigh,
    const float* __restrict__ W,
    const float* __restrict__ bias,
    float* __restrict__ out,
    float* __restrict__ partial)
{
    constexpr int NK = (7 * C) / 32;
    __shared__ __align__(16) union {
        struct { float As[32][132]; float Bs[32][128]; } ab;
        struct { float rs[16][128]; float rq[16][128]; } red;
    } sm;

    const int tid  = threadIdx.x;
    const int bid  = blockIdx.x;
    const int row0 = bid * 128;
    const int ty = tid >> 4, tx = tid & 15;

    float acc[8][8];
#pragma unroll
    for (int a = 0; a < 8; a++)
#pragma unroll
        for (int b = 0; b < 8; b++) acc[a][b] = 0.f;

    // each thread loads half of one A row per k-chunk
    const int lrow = tid >> 1;
    const int half = tid & 1;
    int gnode = row0 + lrow;
    if (gnode >= N_OUT) gnode = N_OUT - 1;
    int nb[7];
#pragma unroll
    for (int j = 0; j < 7; j++) nb[j] = neigh[gnode * 7 + j];

    for (int c = 0; c < NK; ++c) {
        const int gk0 = c * 32;
        const int j   = gk0 / C;                 // chunk fully inside one neighbor
        const int ch0 = gk0 - j * C + half * 16;
        const float* srow = src + (size_t)nb[j] * C + ch0;
#pragma unroll
        for (int u = 0; u < 4; ++u) {
            float4 v = *(const float4*)(srow + u * 4);
            int kk = half * 16 + u * 4;
            sm.ab.As[kk + 0][lrow] = v.x;
            sm.ab.As[kk + 1][lrow] = v.y;
            sm.ab.As[kk + 2][lrow] = v.z;
            sm.ab.As[kk + 3][lrow] = v.w;
        }
#pragma unroll
        for (int u = 0; u < 4; ++u) {
            int off = (tid + u * 256) * 4;
            int br = off >> 7, bc = off & 127;
            *(float4*)&sm.ab.Bs[br][bc] =
                *(const float4*)(W + (size_t)(gk0 + br) * 128 + bc);
        }
        __syncthreads();
#pragma unroll
        for (int kk = 0; kk < 32; ++kk) {
            float4 va  = *(const float4*)&sm.ab.As[kk][ty * 4];
            float4 va2 = *(const float4*)&sm.ab.As[kk][64 + ty * 4];
            float4 vb  = *(const float4*)&sm.ab.Bs[kk][tx * 4];
            float4 vb2 = *(const float4*)&sm.ab.Bs[kk][64 + tx * 4];
            float a0[8] = {va.x, va.y, va.z, va.w, va2.x, va2.y, va2.z, va2.w};
            float b0[8] = {vb.x, vb.y, vb.z, vb.w, vb2.x, vb2.y, vb2.z, vb2.w};
#pragma unroll
            for (int a = 0; a < 8; a++)
#pragma unroll
                for (int b = 0; b < 8; b++)
                    acc[a][b] = fmaf(a0[a], b0[b], acc[a][b]);
        }
        __syncthreads();
    }

    // epilogue: bias add, vectorized store, per-thread BN partials
    float s[8], q[8];
#pragma unroll
    for (int b = 0; b < 8; b++) { s[b] = 0.f; q[b] = 0.f; }
#pragma unroll
    for (int bg = 0; bg < 2; bg++) {
        int gc0 = bg * 64 + tx * 4;
        float4 bv = *(const float4*)(bias + gc0);
        float bvv[4] = {bv.x, bv.y, bv.z, bv.w};
#pragma unroll
        for (int a = 0; a < 8; a++) {
            int grow = row0 + (a >> 2) * 64 + ty * 4 + (a & 3);
            if (grow < N_OUT) {
                float vv[4];
#pragma unroll
                for (int u = 0; u < 4; u++) {
                    float t = acc[a][bg * 4 + u] + bvv[u];
                    vv[u] = t;
                    s[bg * 4 + u] += t;
                    q[bg * 4 + u] += t * t;
                }
                float4 v; v.x = vv[0]; v.y = vv[1]; v.z = vv[2]; v.w = vv[3];
                *(float4*)(out + (size_t)grow * 128 + gc0) = v;
            }
        }
    }
    __syncthreads();
#pragma unroll
    for (int b = 0; b < 8; b++) {
        int gcol = (b >> 2) * 64 + tx * 4 + (b & 3);
        sm.red.rs[ty][gcol] = s[b];
        sm.red.rq[ty][gcol] = q[b];
    }
    __syncthreads();
    if (tid < 128) {
        float S = 0.f, Q = 0.f;
#pragma unroll
        for (int t = 0; t < 16; t++) { S += sm.red.rs[t][tid]; Q += sm.red.rq[t][tid]; }
        partial[(2 * tid + 0) * NBLK + bid] = S;
        partial[(2 * tid + 1) * NBLK + bid] = Q;
    }
}

// ---------------- per-channel BN coefficients ----------------------------
__global__ void stats_kernel(const float* __restrict__ partial,
                             const float* __restrict__ gamma,
                             const float* __restrict__ beta,
                             float* __restrict__ coef)
{
    int c = threadIdx.x;   // 128 threads
    float S = 0.f, Q = 0.f;
    for (int b = 0; b < NBLK; b++) {
        S += partial[(2 * c + 0) * NBLK + b];
        Q += partial[(2 * c + 1) * NBLK + b];
    }
    const float invM = 1.0f / (float)N_OUT;
    float m   = S * invM;
    float var = Q * invM - m * m;
    float istd = rsqrtf(var + 1e-5f);
    float a = gamma[c] * istd;
    coef[2 * c + 0] = a;
    coef[2 * c + 1] = beta[c] - m * a;
}

// ---------------- BN apply + LeakyReLU (float4) ---------------------------
__global__ void apply_kernel(const float* __restrict__ in,
                             const float* __restrict__ coef,
                             float* __restrict__ out, int n4)
{
    int i = blockIdx.x * blockDim.x + threadIdx.x;
    if (i >= n4) return;
    float4 v = ((const float4*)in)[i];
    int c0 = (i * 4) & 127;
    float r[4] = {v.x, v.y, v.z, v.w};
#pragma unroll
    for (int u = 0; u < 4; u++) {
        float a = coef[2 * (c0 + u) + 0];
        float b = coef[2 * (c0 + u) + 1];
        float y = fmaf(a, r[u], b);
        r[u] = (y >= 0.f) ? y : 0.2f * y;
    }
    v.x = r[0]; v.y = r[1]; v.z = r[2]; v.w = r[3];
    ((float4*)out)[i] = v;
}

// ---------------- launch ---------------------------------------------------
extern "C" void kernel_launch(void* const* d_in, const int* in_sizes, int n_in,
                              void* d_out, int out_size) {
    const float* x     = (const float*)d_in[0];
    const int*   neigh = (const int*)d_in[1];
    const int*   po    = (const int*)d_in[2];
    const float* W1    = (const float*)d_in[3];
    const float* b1    = (const float*)d_in[4];
    const float* g1    = (const float*)d_in[5];
    const float* be1   = (const float*)d_in[6];
    const float* W2    = (const float*)d_in[7];
    const float* b2    = (const float*)d_in[8];
    const float* g2    = (const float*)d_in[9];
    const float* be2   = (const float*)d_in[10];
    float* out = (float*)d_out;

    float *pooled, *raw, *h1, *part, *coef;
    cudaGetSymbolAddress((void**)&pooled, g_pooled);
    cudaGetSymbolAddress((void**)&raw,    g_raw);
    cudaGetSymbolAddress((void**)&h1,     g_h1);
    cudaGetSymbolAddress((void**)&part,   g_part);
    cudaGetSymbolAddress((void**)&coef,   g_coef);

    const int n4 = N_OUT * 32;            // N_OUT*128/4
    pool_kernel<<<(N_OUT + 7) / 8, 256>>>(x, po);
    conv_kernel<64><<<NBLK, 256>>>(pooled, neigh, W1, b1, raw, part);
    stats_kernel<<<1, 128>>>(part, g1, be1, coef);
    apply_kernel<<<(n4 + 255) / 256, 256>>>(raw, coef, h1, n4);
    conv_kernel<128><<<NBLK, 256>>>(h1, neigh, W2, b2, raw, part);
    stats_kernel<<<1, 128>>>(part, g2, be2, coef);
    apply_kernel<<<(n4 + 255) / 256, 256>>>(raw, coef, out, n4);
}

// round 8
// speedup vs baseline: 1.5595x; 1.5595x over previous
#include <cuda_runtime.h>
#include <cuda_bf16.h>
#include <cstdint>

#define N_IN   163842
#define N_OUT  40962
#define NBLK   321          // ceil(40962/128)

// ======================= scratch (device globals) =========================
__device__ __align__(256) __nv_bfloat16 g_phi[N_OUT * 64];
__device__ __align__(256) __nv_bfloat16 g_plo[N_OUT * 64];
__device__ __align__(256) __nv_bfloat16 g_h1hi[N_OUT * 128];
__device__ __align__(256) __nv_bfloat16 g_h1lo[N_OUT * 128];
__device__ __align__(256) float g_raw[N_OUT * 128];
__device__ __align__(256) float g_part[2 * 128 * NBLK];
__device__ __align__(256) float g_coef[256];
// preconverted W^T as bf16 hi/lo, row-major [k][128]
__device__ __align__(256) __nv_bfloat16 g_Bhi[896 * 128];
__device__ __align__(256) __nv_bfloat16 g_Blo[896 * 128];

// ======================= asm helpers ======================================
__device__ __forceinline__ uint32_t smem_to_u32(const void* p) {
    uint32_t a;
    asm("{ .reg .u64 t; cvta.to.shared.u64 t, %1; cvt.u32.u64 %0, t; }" : "=r"(a) : "l"(p));
    return a;
}
#define CP16(dst, src) \
    asm volatile("cp.async.cg.shared.global [%0], [%1], 16;" :: "r"(dst), \
                 "l"(__cvta_generic_to_global(src)))
#define CP_COMMIT() asm volatile("cp.async.commit_group;" ::: "memory")
#define CP_WAIT1()  asm volatile("cp.async.wait_group 1;" ::: "memory")
#define CP_WAIT0()  asm volatile("cp.async.wait_group 0;" ::: "memory")

#define LDSM4(r, addr) \
    asm volatile("ldmatrix.sync.aligned.m8n8.x4.shared.b16 {%0,%1,%2,%3}, [%4];" \
        : "=r"((r)[0]), "=r"((r)[1]), "=r"((r)[2]), "=r"((r)[3]) : "r"(addr))
#define LDSM4T(r, addr) \
    asm volatile("ldmatrix.sync.aligned.m8n8.x4.trans.shared.b16 {%0,%1,%2,%3}, [%4];" \
        : "=r"((r)[0]), "=r"((r)[1]), "=r"((r)[2]), "=r"((r)[3]) : "r"(addr))
#define MMA_BF16(d, a, b) \
    asm volatile("mma.sync.aligned.m16n8k16.row.col.f32.bf16.bf16.f32 " \
        "{%0,%1,%2,%3}, {%4,%5,%6,%7}, {%8,%9}, {%0,%1,%2,%3};" \
        : "+f"((d)[0]), "+f"((d)[1]), "+f"((d)[2]), "+f"((d)[3]) \
        : "r"((a)[0]), "r"((a)[1]), "r"((a)[2]), "r"((a)[3]), "r"((b)[0]), "r"((b)[1]))

__device__ __forceinline__ void split_bf16(float v, __nv_bfloat16& hi, __nv_bfloat16& lo) {
    hi = __float2bfloat16(v);
    lo = __float2bfloat16(v - __bfloat162float(hi));
}

// smem layout: per stage Ah(128x72) Al Bh(64x136) Bl, 2 stages, then red bufs
#define A_STRIDE_B 144           // 72 bf16
#define B_STRIDE_B 272           // 136 bf16
#define OFF_AL 18432             // 128*144
#define OFF_BH 36864
#define OFF_BL 54272             // 36864 + 64*272
#define STAGE  71680
#define OFF_RED (2 * STAGE)      // 143360
#define SMEM_TOTAL (OFF_RED + 8192)

// ======================= pool: fp32 gather-mean -> bf16 hi/lo =============
__global__ void pool_kernel(const float* __restrict__ x, const int* __restrict__ po) {
    __shared__ float sh[8 * 448];
    int nb0 = blockIdx.x * 8;
    int tid = threadIdx.x;
    for (int e = tid; e < 8 * 448; e += 256) {
        int ln = e / 448;
        int q  = e - ln * 448;
        int node = nb0 + ln;
        if (node < N_OUT) {
            int r = q >> 6, c = q & 63;
            int srow = po[node * 7 + r];
            sh[e] = x[(size_t)srow * 64 + c];
        }
    }
    __syncthreads();
    for (int e = tid; e < 8 * 64; e += 256) {
        int ln = e >> 6, f = e & 63;
        int node = nb0 + ln;
        if (node < N_OUT) {
            const float* p = &sh[ln * 448 + f * 7];
            float s = (p[0] + p[1] + p[2] + p[3] + p[4] + p[5] + p[6]) * (1.0f / 7.0f);
            __nv_bfloat16 hi, lo; split_bf16(s, hi, lo);
            g_phi[node * 64 + f] = hi;
            g_plo[node * 64 + f] = lo;
        }
    }
}

// ======= prep W: (K,128) fp32 -> bf16 hi/lo, row-major [k][n] =============
__global__ void prepw_kernel(const float* __restrict__ W, int K) {
    int idx = blockIdx.x * 256 + threadIdx.x;
    if (idx >= K * 128) return;
    float v = W[idx];
    __nv_bfloat16 hi, lo; split_bf16(v, hi, lo);
    g_Bhi[idx] = hi;
    g_Blo[idx] = lo;
}

// ====== mma.sync gather-GEMM: (128 x 7C) @ (7C x 128) + bias + BN partials
template <int C, int NC>
__global__ void __launch_bounds__(256) conv_mma_kernel(
    const __nv_bfloat16* __restrict__ shi,
    const __nv_bfloat16* __restrict__ slo,
    const int* __restrict__ neigh,
    const float* __restrict__ bias)
{
    extern __shared__ __align__(128) char sm[];
    const uint32_t sb = smem_to_u32(sm);
    const int t = threadIdx.x;
    const int w = t >> 5, l = t & 31;
    const int wm = w >> 1, wn = w & 1;
    const int bid = blockIdx.x, row0 = bid * 128;

    // gather indices for the row this thread stages
    const int lrow = t >> 1, half = t & 1;
    int cn = row0 + lrow; if (cn >= N_OUT) cn = N_OUT - 1;
    int nb[7];
#pragma unroll
    for (int j = 0; j < 7; j++) nb[j] = neigh[cn * 7 + j];

    const int krow = t >> 2, seg = t & 3;

    auto issue = [&](int c) {
        const int buf = c & 1;
        const uint32_t base = sb + buf * STAGE;
        const int j = (c * 64) / C, ch0 = (c * 64) % C + half * 32;
        const __nv_bfloat16* srh = shi + (size_t)nb[j] * C + ch0;
        const __nv_bfloat16* srl = slo + (size_t)nb[j] * C + ch0;
        const uint32_t da  = base + lrow * A_STRIDE_B + half * 64;
        const uint32_t dal = base + OFF_AL + lrow * A_STRIDE_B + half * 64;
#pragma unroll
        for (int u = 0; u < 4; u++) {
            CP16(da  + u * 16, srh + u * 8);
            CP16(dal + u * 16, srl + u * 8);
        }
        const __nv_bfloat16* sbh = g_Bhi + (size_t)(c * 64 + krow) * 128 + seg * 32;
        const __nv_bfloat16* sbl = g_Blo + (size_t)(c * 64 + krow) * 128 + seg * 32;
        const uint32_t db  = base + OFF_BH + krow * B_STRIDE_B + seg * 64;
        const uint32_t dbl = base + OFF_BL + krow * B_STRIDE_B + seg * 64;
#pragma unroll
        for (int u = 0; u < 4; u++) {
            CP16(db  + u * 16, sbh + u * 8);
            CP16(dbl + u * 16, sbl + u * 8);
        }
        CP_COMMIT();
    };

    float acc[64];
#pragma unroll
    for (int i = 0; i < 64; i++) acc[i] = 0.f;

    issue(0);
    for (int c = 0; c < NC; c++) {
        if (c + 1 < NC) { issue(c + 1); CP_WAIT1(); }
        else            { CP_WAIT0(); }
        __syncthreads();
        const uint32_t base = sb + (c & 1) * STAGE;
        const uint32_t Ah = base, Al = base + OFF_AL;
        const uint32_t Bh = base + OFF_BH, Bl = base + OFF_BL;
#pragma unroll
        for (int ks = 0; ks < 4; ks++) {
            uint32_t ah[2][4], al[2][4];
#pragma unroll
            for (int mf = 0; mf < 2; mf++) {
                uint32_t ao = (uint32_t)(wm * 32 + mf * 16 + (l & 15)) * A_STRIDE_B
                              + ks * 32 + (l >> 4) * 16;
                LDSM4(ah[mf], Ah + ao);
                LDSM4(al[mf], Al + ao);
            }
#pragma unroll
            for (int g = 0; g < 4; g++) {
                uint32_t bh[4], bl[4];
                uint32_t bo = (uint32_t)(ks * 16 + (l & 15)) * B_STRIDE_B
                              + (wn * 64 + g * 16) * 2 + (l >> 4) * 16;
                LDSM4T(bh, Bh + bo);
                LDSM4T(bl, Bl + bo);
#pragma unroll
                for (int mf = 0; mf < 2; mf++) {
#pragma unroll
                    for (int nf2 = 0; nf2 < 2; nf2++) {
                        float* d = &acc[(mf * 8 + g * 2 + nf2) * 4];
                        MMA_BF16(d, ah[mf], &bh[nf2 * 2]);   // hi*hi
                        MMA_BF16(d, ah[mf], &bl[nf2 * 2]);   // hi*lo
                        MMA_BF16(d, al[mf], &bh[nf2 * 2]);   // lo*hi
                    }
                }
            }
        }
        __syncthreads();
    }

    // ---------------- epilogue: bias, store, BN partials ------------------
    float ps[16], pq[16];
#pragma unroll
    for (int i = 0; i < 16; i++) { ps[i] = 0.f; pq[i] = 0.f; }

#pragma unroll
    for (int mf = 0; mf < 2; mf++) {
        int r1 = row0 + wm * 32 + mf * 16 + (l >> 2);
        int r2 = r1 + 8;
        bool v1 = r1 < N_OUT, v2 = r2 < N_OUT;
#pragma unroll
        for (int nf = 0; nf < 8; nf++) {
            int col = wn * 64 + nf * 8 + (l & 3) * 2;
            float b0 = __ldg(bias + col), b1 = __ldg(bias + col + 1);
            float* d = &acc[(mf * 8 + nf) * 4];
            float x0 = d[0] + b0, x1 = d[1] + b1;
            float x2 = d[2] + b0, x3 = d[3] + b1;
            if (v1) {
                float2 v; v.x = x0; v.y = x1;
                *(float2*)(g_raw + (size_t)r1 * 128 + col) = v;
                ps[nf * 2] += x0;     pq[nf * 2] += x0 * x0;
                ps[nf * 2 + 1] += x1; pq[nf * 2 + 1] += x1 * x1;
            }
            if (v2) {
                float2 v; v.x = x2; v.y = x3;
                *(float2*)(g_raw + (size_t)r2 * 128 + col) = v;
                ps[nf * 2] += x2;     pq[nf * 2] += x2 * x2;
                ps[nf * 2 + 1] += x3; pq[nf * 2 + 1] += x3 * x3;
            }
        }
    }
    // reduce over l>>2 (lanes differing in bits 2..4)
#pragma unroll
    for (int i = 0; i < 16; i++) {
#pragma unroll
        for (int o = 4; o <= 16; o <<= 1) {
            ps[i] += __shfl_xor_sync(0xffffffffu, ps[i], o);
            pq[i] += __shfl_xor_sync(0xffffffffu, pq[i], o);
        }
    }
    float* rs = (float*)(sm + OFF_RED);
    float* rq = (float*)(sm + OFF_RED + 4096);
    if (l < 4) {
#pragma unroll
        for (int nf = 0; nf < 8; nf++) {
            int col = wn * 64 + nf * 8 + l * 2;
            rs[w * 128 + col]     = ps[nf * 2];
            rs[w * 128 + col + 1] = ps[nf * 2 + 1];
            rq[w * 128 + col]     = pq[nf * 2];
            rq[w * 128 + col + 1] = pq[nf * 2 + 1];
        }
    }
    __syncthreads();
    if (t < 128) {
        int col = t, wnn = col >> 6;
        float S = 0.f, Q = 0.f;
#pragma unroll
        for (int wm2 = 0; wm2 < 4; wm2++) {
            S += rs[(wm2 * 2 + wnn) * 128 + col];
            Q += rq[(wm2 * 2 + wnn) * 128 + col];
        }
        g_part[(2 * col) * NBLK + bid] = S;
        g_part[(2 * col + 1) * NBLK + bid] = Q;
    }
}

// ---------------- per-channel BN coefficients ----------------------------
__global__ void stats_kernel(const float* __restrict__ gamma,
                             const float* __restrict__ beta)
{
    int c = threadIdx.x;   // 128 threads
    float S = 0.f, Q = 0.f;
    for (int b = 0; b < NBLK; b++) {
        S += g_part[(2 * c + 0) * NBLK + b];
        Q += g_part[(2 * c + 1) * NBLK + b];
    }
    const float invM = 1.0f / (float)N_OUT;
    float m   = S * invM;
    float var = Q * invM - m * m;
    float istd = rsqrtf(var + 1e-5f);
    float a = gamma[c] * istd;
    g_coef[2 * c + 0] = a;
    g_coef[2 * c + 1] = beta[c] - m * a;
}

// -------- BN apply + LeakyReLU -> bf16 hi/lo (intermediate layer) ---------
__global__ void apply_bf16_kernel(int n4)
{
    int i = blockIdx.x * blockDim.x + threadIdx.x;
    if (i >= n4) return;
    float4 v = ((const float4*)g_raw)[i];
    int c0 = (i * 4) & 127;
    float r[4] = {v.x, v.y, v.z, v.w};
    __nv_bfloat16 h[4], lo[4];
#pragma unroll
    for (int u = 0; u < 4; u++) {
        float a = g_coef[2 * (c0 + u) + 0];
        float b = g_coef[2 * (c0 + u) + 1];
        float y = fmaf(a, r[u], b);
        y = (y >= 0.f) ? y : 0.2f * y;
        split_bf16(y, h[u], lo[u]);
    }
    __nv_bfloat162* ph = (__nv_bfloat162*)g_h1hi;
    __nv_bfloat162* pl = (__nv_bfloat162*)g_h1lo;
    ph[i * 2 + 0] = __halves2bfloat162(h[0], h[1]);
    ph[i * 2 + 1] = __halves2bfloat162(h[2], h[3]);
    pl[i * 2 + 0] = __halves2bfloat162(lo[0], lo[1]);
    pl[i * 2 + 1] = __halves2bfloat162(lo[2], lo[3]);
}

// -------- BN apply + LeakyReLU -> fp32 (final output) ---------------------
__global__ void apply_final_kernel(float* __restrict__ out, int n4)
{
    int i = blockIdx.x * blockDim.x + threadIdx.x;
    if (i >= n4) return;
    float4 v = ((const float4*)g_raw)[i];
    int c0 = (i * 4) & 127;
    float r[4] = {v.x, v.y, v.z, v.w};
#pragma unroll
    for (int u = 0; u < 4; u++) {
        float a = g_coef[2 * (c0 + u) + 0];
        float b = g_coef[2 * (c0 + u) + 1];
        float y = fmaf(a, r[u], b);
        r[u] = (y >= 0.f) ? y : 0.2f * y;
    }
    v.x = r[0]; v.y = r[1]; v.z = r[2]; v.w = r[3];
    ((float4*)out)[i] = v;
}

// ---------------- launch ---------------------------------------------------
extern "C" void kernel_launch(void* const* d_in, const int* in_sizes, int n_in,
                              void* d_out, int out_size) {
    const float* x     = (const float*)d_in[0];
    const int*   neigh = (const int*)d_in[1];
    const int*   po    = (const int*)d_in[2];
    const float* W1    = (const float*)d_in[3];
    const float* b1    = (const float*)d_in[4];
    const float* g1    = (const float*)d_in[5];
    const float* be1   = (const float*)d_in[6];
    const float* W2    = (const float*)d_in[7];
    const float* b2    = (const float*)d_in[8];
    const float* g2    = (const float*)d_in[9];
    const float* be2   = (const float*)d_in[10];
    float* out = (float*)d_out;

    cudaFuncSetAttribute(conv_mma_kernel<64, 7>,
                         cudaFuncAttributeMaxDynamicSharedMemorySize, SMEM_TOTAL);
    cudaFuncSetAttribute(conv_mma_kernel<128, 14>,
                         cudaFuncAttributeMaxDynamicSharedMemorySize, SMEM_TOTAL);

    __nv_bfloat16 *phi, *plo, *h1hi, *h1lo;
    cudaGetSymbolAddress((void**)&phi,  g_phi);
    cudaGetSymbolAddress((void**)&plo,  g_plo);
    cudaGetSymbolAddress((void**)&h1hi, g_h1hi);
    cudaGetSymbolAddress((void**)&h1lo, g_h1lo);

    const int n4 = N_OUT * 32;            // N_OUT*128/4

    prepw_kernel<<<(448 * 128 + 255) / 256, 256>>>(W1, 448);
    pool_kernel<<<(N_OUT + 7) / 8, 256>>>(x, po);
    conv_mma_kernel<64, 7><<<NBLK, 256, SMEM_TOTAL>>>(phi, plo, neigh, b1);
    stats_kernel<<<1, 128>>>(g1, be1);
    apply_bf16_kernel<<<(n4 + 255) / 256, 256>>>(n4);
    prepw_kernel<<<(896 * 128 + 255) / 256, 256>>>(W2, 896);
    conv_mma_kernel<128, 14><<<NBLK, 256, SMEM_TOTAL>>>(h1hi, h1lo, neigh, b2);
    stats_kernel<<<1, 128>>>(g2, be2);
    apply_final_kernel<<<(n4 + 255) / 256, 256>>>(out, n4);
}

// round 10
// speedup vs baseline: 1.6094x; 1.0320x over previous
#include <cuda_runtime.h>
#include <cuda_bf16.h>
#include <cstdint>

#define N_IN   163842
#define N_OUT  40962
#define NBLK   321          // ceil(40962/128)

// ======================= scratch (device globals) =========================
__device__ __align__(256) __nv_bfloat16 g_phi[N_OUT * 64];
__device__ __align__(256) __nv_bfloat16 g_plo[N_OUT * 64];
__device__ __align__(256) __nv_bfloat16 g_h1hi[N_OUT * 128];
__device__ __align__(256) __nv_bfloat16 g_h1lo[N_OUT * 128];
__device__ __align__(256) float g_raw[N_OUT * 128];
__device__ __align__(256) float g_part[2 * 128 * NBLK];
__device__ __align__(256) float g_coef[256];
// preconverted W^T as bf16 hi/lo, row-major [k][128]
__device__ __align__(256) __nv_bfloat16 g_Bhi[896 * 128];
__device__ __align__(256) __nv_bfloat16 g_Blo[896 * 128];

// ======================= asm helpers ======================================
__device__ __forceinline__ uint32_t smem_to_u32(const void* p) {
    uint32_t a;
    asm("{ .reg .u64 t; cvta.to.shared.u64 t, %1; cvt.u32.u64 %0, t; }" : "=r"(a) : "l"(p));
    return a;
}
#define CP16(dst, src) \
    asm volatile("cp.async.cg.shared.global [%0], [%1], 16;" :: "r"(dst), \
                 "l"(__cvta_generic_to_global(src)))
#define CP_COMMIT() asm volatile("cp.async.commit_group;" ::: "memory")
#define CP_WAIT1()  asm volatile("cp.async.wait_group 1;" ::: "memory")
#define CP_WAIT0()  asm volatile("cp.async.wait_group 0;" ::: "memory")

#define LDSM4(r, addr) \
    asm volatile("ldmatrix.sync.aligned.m8n8.x4.shared.b16 {%0,%1,%2,%3}, [%4];" \
        : "=r"((r)[0]), "=r"((r)[1]), "=r"((r)[2]), "=r"((r)[3]) : "r"(addr))
#define LDSM4T(r, addr) \
    asm volatile("ldmatrix.sync.aligned.m8n8.x4.trans.shared.b16 {%0,%1,%2,%3}, [%4];" \
        : "=r"((r)[0]), "=r"((r)[1]), "=r"((r)[2]), "=r"((r)[3]) : "r"(addr))
#define MMA_BF16(d, a, b) \
    asm volatile("mma.sync.aligned.m16n8k16.row.col.f32.bf16.bf16.f32 " \
        "{%0,%1,%2,%3}, {%4,%5,%6,%7}, {%8,%9}, {%0,%1,%2,%3};" \
        : "+f"((d)[0]), "+f"((d)[1]), "+f"((d)[2]), "+f"((d)[3]) \
        : "r"((a)[0]), "r"((a)[1]), "r"((a)[2]), "r"((a)[3]), "r"((b)[0]), "r"((b)[1]))

__device__ __forceinline__ void split_bf16(float v, __nv_bfloat16& hi, __nv_bfloat16& lo) {
    hi = __float2bfloat16(v);
    lo = __float2bfloat16(v - __bfloat162float(hi));
}

// smem layout: per stage Ah(128x72) Al Bh(64x136) Bl, 2 stages, then red bufs
#define A_STRIDE_B 144           // 72 bf16
#define B_STRIDE_B 272           // 136 bf16
#define OFF_AL 18432             // 128*144
#define OFF_BH 36864
#define OFF_BL 54272             // 36864 + 64*272
#define STAGE  71680
#define OFF_RED (2 * STAGE)      // 143360
#define SMEM_TOTAL (OFF_RED + 8192)

// ======================= pool: fp32 gather-mean -> bf16 hi/lo =============
__global__ void pool_kernel(const float* __restrict__ x, const int* __restrict__ po) {
    __shared__ float sh[8 * 448];
    int nb0 = blockIdx.x * 8;
    int tid = threadIdx.x;
    for (int e = tid; e < 8 * 448; e += 256) {
        int ln = e / 448;
        int q  = e - ln * 448;
        int node = nb0 + ln;
        if (node < N_OUT) {
            int r = q >> 6, c = q & 63;
            int srow = po[node * 7 + r];
            sh[e] = x[(size_t)srow * 64 + c];
        }
    }
    __syncthreads();
    for (int e = tid; e < 8 * 64; e += 256) {
        int ln = e >> 6, f = e & 63;
        int node = nb0 + ln;
        if (node < N_OUT) {
            const float* p = &sh[ln * 448 + f * 7];
            float s = (p[0] + p[1] + p[2] + p[3] + p[4] + p[5] + p[6]) * (1.0f / 7.0f);
            __nv_bfloat16 hi, lo; split_bf16(s, hi, lo);
            g_phi[node * 64 + f] = hi;
            g_plo[node * 64 + f] = lo;
        }
    }
}

// ======= prep W: (K,128) fp32 -> bf16 hi/lo, row-major [k][n] =============
__global__ void prepw_kernel(const float* __restrict__ W, int K) {
    int idx = blockIdx.x * 256 + threadIdx.x;
    if (idx >= K * 128) return;
    float v = W[idx];
    __nv_bfloat16 hi, lo; split_bf16(v, hi, lo);
    g_Bhi[idx] = hi;
    g_Blo[idx] = lo;
}

// ====== mma.sync gather-GEMM: (128 x 7C) @ (7C x 128) + bias + BN partials
template <int C, int NC>
__global__ void __launch_bounds__(256) conv_mma_kernel(
    const __nv_bfloat16* __restrict__ shi,
    const __nv_bfloat16* __restrict__ slo,
    const int* __restrict__ neigh,
    const float* __restrict__ bias)
{
    extern __shared__ __align__(128) char sm[];
    const uint32_t sb = smem_to_u32(sm);
    const int t = threadIdx.x;
    const int w = t >> 5, l = t & 31;
    const int wm = w >> 1, wn = w & 1;
    const int bid = blockIdx.x, row0 = bid * 128;

    // gather indices for the row this thread stages
    const int lrow = t >> 1, half = t & 1;
    int cn = row0 + lrow; if (cn >= N_OUT) cn = N_OUT - 1;
    int nb[7];
#pragma unroll
    for (int j = 0; j < 7; j++) nb[j] = neigh[cn * 7 + j];

    const int krow = t >> 2, seg = t & 3;

    auto issue = [&](int c) {
        const int buf = c & 1;
        const uint32_t base = sb + buf * STAGE;
        const int j = (c * 64) / C, ch0 = (c * 64) % C + half * 32;
        const __nv_bfloat16* srh = shi + (size_t)nb[j] * C + ch0;
        const __nv_bfloat16* srl = slo + (size_t)nb[j] * C + ch0;
        const uint32_t da  = base + lrow * A_STRIDE_B + half * 64;
        const uint32_t dal = base + OFF_AL + lrow * A_STRIDE_B + half * 64;
#pragma unroll
        for (int u = 0; u < 4; u++) {
            CP16(da  + u * 16, srh + u * 8);
            CP16(dal + u * 16, srl + u * 8);
        }
        const __nv_bfloat16* sbh = g_Bhi + (size_t)(c * 64 + krow) * 128 + seg * 32;
        const __nv_bfloat16* sbl = g_Blo + (size_t)(c * 64 + krow) * 128 + seg * 32;
        const uint32_t db  = base + OFF_BH + krow * B_STRIDE_B + seg * 64;
        const uint32_t dbl = base + OFF_BL + krow * B_STRIDE_B + seg * 64;
#pragma unroll
        for (int u = 0; u < 4; u++) {
            CP16(db  + u * 16, sbh + u * 8);
            CP16(dbl + u * 16, sbl + u * 8);
        }
        CP_COMMIT();
    };

    float acc[64];
#pragma unroll
    for (int i = 0; i < 64; i++) acc[i] = 0.f;

    issue(0);
    for (int c = 0; c < NC; c++) {
        if (c + 1 < NC) { issue(c + 1); CP_WAIT1(); }
        else            { CP_WAIT0(); }
        __syncthreads();
        const uint32_t base = sb + (c & 1) * STAGE;
        const uint32_t Ah = base, Al = base + OFF_AL;
        const uint32_t Bh = base + OFF_BH, Bl = base + OFF_BL;
#pragma unroll
        for (int ks = 0; ks < 4; ks++) {
            uint32_t ah[2][4], al[2][4];
#pragma unroll
            for (int mf = 0; mf < 2; mf++) {
                uint32_t ao = (uint32_t)(wm * 32 + mf * 16 + (l & 15)) * A_STRIDE_B
                              + ks * 32 + (l >> 4) * 16;
                LDSM4(ah[mf], Ah + ao);
                LDSM4(al[mf], Al + ao);
            }
#pragma unroll
            for (int g = 0; g < 4; g++) {
                uint32_t bh[4], bl[4];
                uint32_t bo = (uint32_t)(ks * 16 + (l & 15)) * B_STRIDE_B
                              + (wn * 64 + g * 16) * 2 + (l >> 4) * 16;
                LDSM4T(bh, Bh + bo);
                LDSM4T(bl, Bl + bo);
#pragma unroll
                for (int mf = 0; mf < 2; mf++) {
#pragma unroll
                    for (int nf2 = 0; nf2 < 2; nf2++) {
                        float* d = &acc[(mf * 8 + g * 2 + nf2) * 4];
                        MMA_BF16(d, ah[mf], &bh[nf2 * 2]);   // hi*hi
                        MMA_BF16(d, ah[mf], &bl[nf2 * 2]);   // hi*lo
                        MMA_BF16(d, al[mf], &bh[nf2 * 2]);   // lo*hi
                    }
                }
            }
        }
        __syncthreads();
    }

    // ---------------- epilogue: bias, store, BN partials ------------------
    float ps[16], pq[16];
#pragma unroll
    for (int i = 0; i < 16; i++) { ps[i] = 0.f; pq[i] = 0.f; }

#pragma unroll
    for (int mf = 0; mf < 2; mf++) {
        int r1 = row0 + wm * 32 + mf * 16 + (l >> 2);
        int r2 = r1 + 8;
        bool v1 = r1 < N_OUT, v2 = r2 < N_OUT;
#pragma unroll
        for (int nf = 0; nf < 8; nf++) {
            int col = wn * 64 + nf * 8 + (l & 3) * 2;
            float b0 = __ldg(bias + col), b1 = __ldg(bias + col + 1);
            float* d = &acc[(mf * 8 + nf) * 4];
            float x0 = d[0] + b0, x1 = d[1] + b1;
            float x2 = d[2] + b0, x3 = d[3] + b1;
            if (v1) {
                float2 v; v.x = x0; v.y = x1;
                *(float2*)(g_raw + (size_t)r1 * 128 + col) = v;
                ps[nf * 2] += x0;     pq[nf * 2] += x0 * x0;
                ps[nf * 2 + 1] += x1; pq[nf * 2 + 1] += x1 * x1;
            }
            if (v2) {
                float2 v; v.x = x2; v.y = x3;
                *(float2*)(g_raw + (size_t)r2 * 128 + col) = v;
                ps[nf * 2] += x2;     pq[nf * 2] += x2 * x2;
                ps[nf * 2 + 1] += x3; pq[nf * 2 + 1] += x3 * x3;
            }
        }
    }
    // reduce over l>>2 (lanes differing in bits 2..4)
#pragma unroll
    for (int i = 0; i < 16; i++) {
#pragma unroll
        for (int o = 4; o <= 16; o <<= 1) {
            ps[i] += __shfl_xor_sync(0xffffffffu, ps[i], o);
            pq[i] += __shfl_xor_sync(0xffffffffu, pq[i], o);
        }
    }
    float* rs = (float*)(sm + OFF_RED);
    float* rq = (float*)(sm + OFF_RED + 4096);
    if (l < 4) {
#pragma unroll
        for (int nf = 0; nf < 8; nf++) {
            int col = wn * 64 + nf * 8 + l * 2;
            rs[w * 128 + col]     = ps[nf * 2];
            rs[w * 128 + col + 1] = ps[nf * 2 + 1];
            rq[w * 128 + col]     = pq[nf * 2];
            rq[w * 128 + col + 1] = pq[nf * 2 + 1];
        }
    }
    __syncthreads();
    if (t < 128) {
        int col = t, wnn = col >> 6;
        float S = 0.f, Q = 0.f;
#pragma unroll
        for (int wm2 = 0; wm2 < 4; wm2++) {
            S += rs[(wm2 * 2 + wnn) * 128 + col];
            Q += rq[(wm2 * 2 + wnn) * 128 + col];
        }
        g_part[(2 * col) * NBLK + bid] = S;
        g_part[(2 * col + 1) * NBLK + bid] = Q;
    }
}

// ------- per-channel BN coefficients: one block per channel ---------------
__global__ void __launch_bounds__(128) stats_kernel(const float* __restrict__ gamma,
                                                    const float* __restrict__ beta)
{
    __shared__ float shS[4], shQ[4];
    const int c = blockIdx.x;        // 128 blocks, one per channel
    const int t = threadIdx.x;       // 128 threads
    const float* pS = &g_part[(2 * c + 0) * NBLK];
    const float* pQ = &g_part[(2 * c + 1) * NBLK];
    float S = 0.f, Q = 0.f;
    for (int b = t; b < NBLK; b += 128) { S += pS[b]; Q += pQ[b]; }
#pragma unroll
    for (int o = 16; o > 0; o >>= 1) {
        S += __shfl_xor_sync(0xffffffffu, S, o);
        Q += __shfl_xor_sync(0xffffffffu, Q, o);
    }
    if ((t & 31) == 0) { shS[t >> 5] = S; shQ[t >> 5] = Q; }
    __syncthreads();
    if (t == 0) {
        S = shS[0] + shS[1] + shS[2] + shS[3];
        Q = shQ[0] + shQ[1] + shQ[2] + shQ[3];
        const float invM = 1.0f / (float)N_OUT;
        float m   = S * invM;
        float var = Q * invM - m * m;
        float istd = rsqrtf(var + 1e-5f);
        float a = gamma[c] * istd;
        g_coef[2 * c + 0] = a;
        g_coef[2 * c + 1] = beta[c] - m * a;
    }
}

// -------- BN apply + LeakyReLU -> bf16 hi/lo (intermediate layer) ---------
__global__ void apply_bf16_kernel(int n4)
{
    int i = blockIdx.x * blockDim.x + threadIdx.x;
    if (i >= n4) return;
    float4 v = ((const float4*)g_raw)[i];
    int c0 = (i * 4) & 127;
    float r[4] = {v.x, v.y, v.z, v.w};
    __nv_bfloat16 h[4], lo[4];
#pragma unroll
    for (int u = 0; u < 4; u++) {
        float a = __ldg(&g_coef[2 * (c0 + u) + 0]);
        float b = __ldg(&g_coef[2 * (c0 + u) + 1]);
        float y = fmaf(a, r[u], b);
        y = (y >= 0.f) ? y : 0.2f * y;
        split_bf16(y, h[u], lo[u]);
    }
    __nv_bfloat162* ph = (__nv_bfloat162*)g_h1hi;
    __nv_bfloat162* pl = (__nv_bfloat162*)g_h1lo;
    ph[i * 2 + 0] = __halves2bfloat162(h[0], h[1]);
    ph[i * 2 + 1] = __halves2bfloat162(h[2], h[3]);
    pl[i * 2 + 0] = __halves2bfloat162(lo[0], lo[1]);
    pl[i * 2 + 1] = __halves2bfloat162(lo[2], lo[3]);
}

// -------- BN apply + LeakyReLU -> fp32 (final output) ---------------------
__global__ void apply_final_kernel(float* __restrict__ out, int n4)
{
    int i = blockIdx.x * blockDim.x + threadIdx.x;
    if (i >= n4) return;
    float4 v = ((const float4*)g_raw)[i];
    int c0 = (i * 4) & 127;
    float r[4] = {v.x, v.y, v.z, v.w};
#pragma unroll
    for (int u = 0; u < 4; u++) {
        float a = __ldg(&g_coef[2 * (c0 + u) + 0]);
        float b = __ldg(&g_coef[2 * (c0 + u) + 1]);
        float y = fmaf(a, r[u], b);
        r[u] = (y >= 0.f) ? y : 0.2f * y;
    }
    v.x = r[0]; v.y = r[1]; v.z = r[2]; v.w = r[3];
    ((float4*)out)[i] = v;
}

// ---------------- launch ---------------------------------------------------
extern "C" void kernel_launch(void* const* d_in, const int* in_sizes, int n_in,
                              void* d_out, int out_size) {
    const float* x     = (const float*)d_in[0];
    const int*   neigh = (const int*)d_in[1];
    const int*   po    = (const int*)d_in[2];
    const float* W1    = (const float*)d_in[3];
    const float* b1    = (const float*)d_in[4];
    const float* g1    = (const float*)d_in[5];
    const float* be1   = (const float*)d_in[6];
    const float* W2    = (const float*)d_in[7];
    const float* b2    = (const float*)d_in[8];
    const float* g2    = (const float*)d_in[9];
    const float* be2   = (const float*)d_in[10];
    float* out = (float*)d_out;

    cudaFuncSetAttribute(conv_mma_kernel<64, 7>,
                         cudaFuncAttributeMaxDynamicSharedMemorySize, SMEM_TOTAL);
    cudaFuncSetAttribute(conv_mma_kernel<128, 14>,
                         cudaFuncAttributeMaxDynamicSharedMemorySize, SMEM_TOTAL);

    __nv_bfloat16 *phi, *plo, *h1hi, *h1lo;
    cudaGetSymbolAddress((void**)&phi,  g_phi);
    cudaGetSymbolAddress((void**)&plo,  g_plo);
    cudaGetSymbolAddress((void**)&h1hi, g_h1hi);
    cudaGetSymbolAddress((void**)&h1lo, g_h1lo);

    const int n4 = N_OUT * 32;            // N_OUT*128/4

    prepw_kernel<<<(448 * 128 + 255) / 256, 256>>>(W1, 448);
    pool_kernel<<<(N_OUT + 7) / 8, 256>>>(x, po);
    conv_mma_kernel<64, 7><<<NBLK, 256, SMEM_TOTAL>>>(phi, plo, neigh, b1);
    stats_kernel<<<128, 128>>>(g1, be1);
    apply_bf16_kernel<<<(n4 + 255) / 256, 256>>>(n4);
    prepw_kernel<<<(896 * 128 + 255) / 256, 256>>>(W2, 896);
    conv_mma_kernel<128, 14><<<NBLK, 256, SMEM_TOTAL>>>(h1hi, h1lo, neigh, b2);
    stats_kernel<<<128, 128>>>(g2, be2);
    apply_final_kernel<<<(n4 + 255) / 256, 256>>>(out, n4);
}

// round 11
// speedup vs baseline: 1.8597x; 1.1556x over previous
#include <cuda_runtime.h>
#include <cuda_bf16.h>
#include <cstdint>

#define N_IN   163842
#define N_OUT  40962
#define NBLK   321          // ceil(40962/128)

// ======================= scratch (device globals) =========================
__device__ __align__(256) __nv_bfloat16 g_phi[N_OUT * 64];
__device__ __align__(256) __nv_bfloat16 g_plo[N_OUT * 64];
__device__ __align__(256) __nv_bfloat16 g_h1hi[N_OUT * 128];
__device__ __align__(256) __nv_bfloat16 g_h1lo[N_OUT * 128];
__device__ __align__(256) float g_raw[N_OUT * 128];
__device__ __align__(256) float g_part[2 * 128 * NBLK];
__device__ __align__(256) float g_coef[256];
// preconverted W^T as bf16 hi/lo, row-major [k][128]
__device__ __align__(256) __nv_bfloat16 g_Bhi[896 * 128];
__device__ __align__(256) __nv_bfloat16 g_Blo[896 * 128];

// ======================= asm helpers ======================================
__device__ __forceinline__ uint32_t smem_to_u32(const void* p) {
    uint32_t a;
    asm("{ .reg .u64 t; cvta.to.shared.u64 t, %1; cvt.u32.u64 %0, t; }" : "=r"(a) : "l"(p));
    return a;
}
#define CP16(dst, src) \
    asm volatile("cp.async.cg.shared.global [%0], [%1], 16;" :: "r"(dst), \
                 "l"(__cvta_generic_to_global(src)))
#define CP_COMMIT() asm volatile("cp.async.commit_group;" ::: "memory")
#define CP_WAIT1()  asm volatile("cp.async.wait_group 1;" ::: "memory")
#define CP_WAIT0()  asm volatile("cp.async.wait_group 0;" ::: "memory")

#define LDSM4(r, addr) \
    asm volatile("ldmatrix.sync.aligned.m8n8.x4.shared.b16 {%0,%1,%2,%3}, [%4];" \
        : "=r"((r)[0]), "=r"((r)[1]), "=r"((r)[2]), "=r"((r)[3]) : "r"(addr))
#define LDSM4T(r, addr) \
    asm volatile("ldmatrix.sync.aligned.m8n8.x4.trans.shared.b16 {%0,%1,%2,%3}, [%4];" \
        : "=r"((r)[0]), "=r"((r)[1]), "=r"((r)[2]), "=r"((r)[3]) : "r"(addr))
#define MMA_BF16(d, a, b) \
    asm volatile("mma.sync.aligned.m16n8k16.row.col.f32.bf16.bf16.f32 " \
        "{%0,%1,%2,%3}, {%4,%5,%6,%7}, {%8,%9}, {%0,%1,%2,%3};" \
        : "+f"((d)[0]), "+f"((d)[1]), "+f"((d)[2]), "+f"((d)[3]) \
        : "r"((a)[0]), "r"((a)[1]), "r"((a)[2]), "r"((a)[3]), "r"((b)[0]), "r"((b)[1]))

__device__ __forceinline__ void split_bf16(float v, __nv_bfloat16& hi, __nv_bfloat16& lo) {
    hi = __float2bfloat16(v);
    lo = __float2bfloat16(v - __bfloat162float(hi));
}

// smem layout: per stage Ah(128x80B) Al Bh(32x272B) Bl, 2 stages, then red
// BK=32 per chunk -> stage 37888B, 2 CTAs/SM.
#define A_STRIDE_B 80            // 32 bf16 data + 8 bf16 pad
#define B_STRIDE_B 272           // 128 bf16 data + 8 bf16 pad
#define OFF_AL 10240             // 128*80
#define OFF_BH 20480
#define OFF_BL 29184             // 20480 + 32*272
#define STAGE  37888
#define OFF_RED (2 * STAGE)      // 75776
#define SMEM_TOTAL (OFF_RED + 8192)   // 83968

// ======================= pool: fp32 gather-mean -> bf16 hi/lo =============
__global__ void pool_kernel(const float* __restrict__ x, const int* __restrict__ po) {
    __shared__ float sh[8 * 448];
    int nb0 = blockIdx.x * 8;
    int tid = threadIdx.x;
    for (int e = tid; e < 8 * 448; e += 256) {
        int ln = e / 448;
        int q  = e - ln * 448;
        int node = nb0 + ln;
        if (node < N_OUT) {
            int r = q >> 6, c = q & 63;
            int srow = po[node * 7 + r];
            sh[e] = x[(size_t)srow * 64 + c];
        }
    }
    __syncthreads();
    for (int e = tid; e < 8 * 64; e += 256) {
        int ln = e >> 6, f = e & 63;
        int node = nb0 + ln;
        if (node < N_OUT) {
            const float* p = &sh[ln * 448 + f * 7];
            float s = (p[0] + p[1] + p[2] + p[3] + p[4] + p[5] + p[6]) * (1.0f / 7.0f);
            __nv_bfloat16 hi, lo; split_bf16(s, hi, lo);
            g_phi[node * 64 + f] = hi;
            g_plo[node * 64 + f] = lo;
        }
    }
}

// ======= prep W: (K,128) fp32 -> bf16 hi/lo, row-major [k][n] =============
__global__ void prepw_kernel(const float* __restrict__ W, int K) {
    int idx = blockIdx.x * 256 + threadIdx.x;
    if (idx >= K * 128) return;
    float v = W[idx];
    __nv_bfloat16 hi, lo; split_bf16(v, hi, lo);
    g_Bhi[idx] = hi;
    g_Blo[idx] = lo;
}

// ====== mma.sync gather-GEMM: (128 x 7C) @ (7C x 128) + bias + BN partials
// BK=32 per chunk, 2 stages, 2 CTAs/SM.
template <int C, int NC>
__global__ void __launch_bounds__(256, 2) conv_mma_kernel(
    const __nv_bfloat16* __restrict__ shi,
    const __nv_bfloat16* __restrict__ slo,
    const int* __restrict__ neigh,
    const float* __restrict__ bias)
{
    extern __shared__ __align__(128) char sm[];
    const uint32_t sb = smem_to_u32(sm);
    const int t = threadIdx.x;
    const int w = t >> 5, l = t & 31;
    const int wm = w >> 1, wn = w & 1;
    const int bid = blockIdx.x, row0 = bid * 128;

    // gather indices for the row this thread stages (A: 2 threads per row)
    const int arow = t >> 1, ahalf = t & 1;
    int cn = row0 + arow; if (cn >= N_OUT) cn = N_OUT - 1;
    int nb[7];
#pragma unroll
    for (int j = 0; j < 7; j++) nb[j] = neigh[cn * 7 + j];

    const int brow = t >> 3, bseg = t & 7;    // B: 8 threads per row

    auto issue = [&](int c) {
        const int buf = c & 1;
        const uint32_t base = sb + buf * STAGE;
        const int j = (c * 32) / C, ch0 = (c * 32) % C + ahalf * 16;
        const __nv_bfloat16* srh = shi + (size_t)nb[j] * C + ch0;
        const __nv_bfloat16* srl = slo + (size_t)nb[j] * C + ch0;
        const uint32_t da  = base + arow * A_STRIDE_B + ahalf * 32;
        const uint32_t dal = base + OFF_AL + arow * A_STRIDE_B + ahalf * 32;
        CP16(da,       srh);
        CP16(da  + 16, srh + 8);
        CP16(dal,      srl);
        CP16(dal + 16, srl + 8);
        const __nv_bfloat16* sbh = g_Bhi + (size_t)(c * 32 + brow) * 128 + bseg * 16;
        const __nv_bfloat16* sbl = g_Blo + (size_t)(c * 32 + brow) * 128 + bseg * 16;
        const uint32_t db  = base + OFF_BH + brow * B_STRIDE_B + bseg * 32;
        const uint32_t dbl = base + OFF_BL + brow * B_STRIDE_B + bseg * 32;
        CP16(db,       sbh);
        CP16(db  + 16, sbh + 8);
        CP16(dbl,      sbl);
        CP16(dbl + 16, sbl + 8);
        CP_COMMIT();
    };

    float acc[64];
#pragma unroll
    for (int i = 0; i < 64; i++) acc[i] = 0.f;

    issue(0);
    for (int c = 0; c < NC; c++) {
        if (c + 1 < NC) { issue(c + 1); CP_WAIT1(); }
        else            { CP_WAIT0(); }
        __syncthreads();
        const uint32_t base = sb + (c & 1) * STAGE;
        const uint32_t Ah = base, Al = base + OFF_AL;
        const uint32_t Bh = base + OFF_BH, Bl = base + OFF_BL;
#pragma unroll
        for (int ks = 0; ks < 2; ks++) {
            uint32_t ah[2][4], al[2][4];
#pragma unroll
            for (int mf = 0; mf < 2; mf++) {
                uint32_t ao = (uint32_t)(wm * 32 + mf * 16 + (l & 15)) * A_STRIDE_B
                              + ks * 32 + (l >> 4) * 16;
                LDSM4(ah[mf], Ah + ao);
                LDSM4(al[mf], Al + ao);
            }
#pragma unroll
            for (int g = 0; g < 4; g++) {
                uint32_t bh[4], bl[4];
                uint32_t bo = (uint32_t)(ks * 16 + (l & 15)) * B_STRIDE_B
                              + (wn * 64 + g * 16) * 2 + (l >> 4) * 16;
                LDSM4T(bh, Bh + bo);
                LDSM4T(bl, Bl + bo);
#pragma unroll
                for (int mf = 0; mf < 2; mf++) {
#pragma unroll
                    for (int nf2 = 0; nf2 < 2; nf2++) {
                        float* d = &acc[(mf * 8 + g * 2 + nf2) * 4];
                        MMA_BF16(d, ah[mf], &bh[nf2 * 2]);   // hi*hi
                        MMA_BF16(d, ah[mf], &bl[nf2 * 2]);   // hi*lo
                        MMA_BF16(d, al[mf], &bh[nf2 * 2]);   // lo*hi
                    }
                }
            }
        }
        __syncthreads();
    }

    // ---------------- epilogue: bias, store, BN partials ------------------
    float ps[16], pq[16];
#pragma unroll
    for (int i = 0; i < 16; i++) { ps[i] = 0.f; pq[i] = 0.f; }

#pragma unroll
    for (int mf = 0; mf < 2; mf++) {
        int r1 = row0 + wm * 32 + mf * 16 + (l >> 2);
        int r2 = r1 + 8;
        bool v1 = r1 < N_OUT, v2 = r2 < N_OUT;
#pragma unroll
        for (int nf = 0; nf < 8; nf++) {
            int col = wn * 64 + nf * 8 + (l & 3) * 2;
            float b0 = __ldg(bias + col), b1 = __ldg(bias + col + 1);
            float* d = &acc[(mf * 8 + nf) * 4];
            float x0 = d[0] + b0, x1 = d[1] + b1;
            float x2 = d[2] + b0, x3 = d[3] + b1;
            if (v1) {
                float2 v; v.x = x0; v.y = x1;
                *(float2*)(g_raw + (size_t)r1 * 128 + col) = v;
                ps[nf * 2] += x0;     pq[nf * 2] += x0 * x0;
                ps[nf * 2 + 1] += x1; pq[nf * 2 + 1] += x1 * x1;
            }
            if (v2) {
                float2 v; v.x = x2; v.y = x3;
                *(float2*)(g_raw + (size_t)r2 * 128 + col) = v;
                ps[nf * 2] += x2;     pq[nf * 2] += x2 * x2;
                ps[nf * 2 + 1] += x3; pq[nf * 2 + 1] += x3 * x3;
            }
        }
    }
    // reduce over l>>2 (lanes differing in bits 2..4)
#pragma unroll
    for (int i = 0; i < 16; i++) {
#pragma unroll
        for (int o = 4; o <= 16; o <<= 1) {
            ps[i] += __shfl_xor_sync(0xffffffffu, ps[i], o);
            pq[i] += __shfl_xor_sync(0xffffffffu, pq[i], o);
        }
    }
    float* rs = (float*)(sm + OFF_RED);
    float* rq = (float*)(sm + OFF_RED + 4096);
    if (l < 4) {
#pragma unroll
        for (int nf = 0; nf < 8; nf++) {
            int col = wn * 64 + nf * 8 + l * 2;
            rs[w * 128 + col]     = ps[nf * 2];
            rs[w * 128 + col + 1] = ps[nf * 2 + 1];
            rq[w * 128 + col]     = pq[nf * 2];
            rq[w * 128 + col + 1] = pq[nf * 2 + 1];
        }
    }
    __syncthreads();
    if (t < 128) {
        int col = t, wnn = col >> 6;
        float S = 0.f, Q = 0.f;
#pragma unroll
        for (int wm2 = 0; wm2 < 4; wm2++) {
            S += rs[(wm2 * 2 + wnn) * 128 + col];
            Q += rq[(wm2 * 2 + wnn) * 128 + col];
        }
        g_part[(2 * col) * NBLK + bid] = S;
        g_part[(2 * col + 1) * NBLK + bid] = Q;
    }
}

// ------- per-channel BN coefficients: one block per channel ---------------
__global__ void __launch_bounds__(128) stats_kernel(const float* __restrict__ gamma,
                                                    const float* __restrict__ beta)
{
    __shared__ float shS[4], shQ[4];
    const int c = blockIdx.x;        // 128 blocks, one per channel
    const int t = threadIdx.x;       // 128 threads
    const float* pS = &g_part[(2 * c + 0) * NBLK];
    const float* pQ = &g_part[(2 * c + 1) * NBLK];
    float S = 0.f, Q = 0.f;
    for (int b = t; b < NBLK; b += 128) { S += pS[b]; Q += pQ[b]; }
#pragma unroll
    for (int o = 16; o > 0; o >>= 1) {
        S += __shfl_xor_sync(0xffffffffu, S, o);
        Q += __shfl_xor_sync(0xffffffffu, Q, o);
    }
    if ((t & 31) == 0) { shS[t >> 5] = S; shQ[t >> 5] = Q; }
    __syncthreads();
    if (t == 0) {
        S = shS[0] + shS[1] + shS[2] + shS[3];
        Q = shQ[0] + shQ[1] + shQ[2] + shQ[3];
        const float invM = 1.0f / (float)N_OUT;
        float m   = S * invM;
        float var = Q * invM - m * m;
        float istd = rsqrtf(var + 1e-5f);
        float a = gamma[c] * istd;
        g_coef[2 * c + 0] = a;
        g_coef[2 * c + 1] = beta[c] - m * a;
    }
}

// -------- BN apply + LeakyReLU -> bf16 hi/lo (intermediate layer) ---------
__global__ void apply_bf16_kernel(int n4)
{
    int i = blockIdx.x * blockDim.x + threadIdx.x;
    if (i >= n4) return;
    float4 v = ((const float4*)g_raw)[i];
    int c0 = (i * 4) & 127;
    float r[4] = {v.x, v.y, v.z, v.w};
    __nv_bfloat16 h[4], lo[4];
#pragma unroll
    for (int u = 0; u < 4; u++) {
        float a = __ldg(&g_coef[2 * (c0 + u) + 0]);
        float b = __ldg(&g_coef[2 * (c0 + u) + 1]);
        float y = fmaf(a, r[u], b);
        y = (y >= 0.f) ? y : 0.2f * y;
        split_bf16(y, h[u], lo[u]);
    }
    __nv_bfloat162* ph = (__nv_bfloat162*)g_h1hi;
    __nv_bfloat162* pl = (__nv_bfloat162*)g_h1lo;
    ph[i * 2 + 0] = __halves2bfloat162(h[0], h[1]);
    ph[i * 2 + 1] = __halves2bfloat162(h[2], h[3]);
    pl[i * 2 + 0] = __halves2bfloat162(lo[0], lo[1]);
    pl[i * 2 + 1] = __halves2bfloat162(lo[2], lo[3]);
}

// -------- BN apply + LeakyReLU -> fp32 (final output) ---------------------
__global__ void apply_final_kernel(float* __restrict__ out, int n4)
{
    int i = blockIdx.x * blockDim.x + threadIdx.x;
    if (i >= n4) return;
    float4 v = ((const float4*)g_raw)[i];
    int c0 = (i * 4) & 127;
    float r[4] = {v.x, v.y, v.z, v.w};
#pragma unroll
    for (int u = 0; u < 4; u++) {
        float a = __ldg(&g_coef[2 * (c0 + u) + 0]);
        float b = __ldg(&g_coef[2 * (c0 + u) + 1]);
        float y = fmaf(a, r[u], b);
        r[u] = (y >= 0.f) ? y : 0.2f * y;
    }
    v.x = r[0]; v.y = r[1]; v.z = r[2]; v.w = r[3];
    ((float4*)out)[i] = v;
}

// ---------------- launch ---------------------------------------------------
extern "C" void kernel_launch(void* const* d_in, const int* in_sizes, int n_in,
                              void* d_out, int out_size) {
    const float* x     = (const float*)d_in[0];
    const int*   neigh = (const int*)d_in[1];
    const int*   po    = (const int*)d_in[2];
    const float* W1    = (const float*)d_in[3];
    const float* b1    = (const float*)d_in[4];
    const float* g1    = (const float*)d_in[5];
    const float* be1   = (const float*)d_in[6];
    const float* W2    = (const float*)d_in[7];
    const float* b2    = (const float*)d_in[8];
    const float* g2    = (const float*)d_in[9];
    const float* be2   = (const float*)d_in[10];
    float* out = (float*)d_out;

    cudaFuncSetAttribute(conv_mma_kernel<64, 14>,
                         cudaFuncAttributeMaxDynamicSharedMemorySize, SMEM_TOTAL);
    cudaFuncSetAttribute(conv_mma_kernel<128, 28>,
                         cudaFuncAttributeMaxDynamicSharedMemorySize, SMEM_TOTAL);

    __nv_bfloat16 *phi, *plo, *h1hi, *h1lo;
    cudaGetSymbolAddress((void**)&phi,  g_phi);
    cudaGetSymbolAddress((void**)&plo,  g_plo);
    cudaGetSymbolAddress((void**)&h1hi, g_h1hi);
    cudaGetSymbolAddress((void**)&h1lo, g_h1lo);

    const int n4 = N_OUT * 32;            // N_OUT*128/4

    prepw_kernel<<<(448 * 128 + 255) / 256, 256>>>(W1, 448);
    pool_kernel<<<(N_OUT + 7) / 8, 256>>>(x, po);
    conv_mma_kernel<64, 14><<<NBLK, 256, SMEM_TOTAL>>>(phi, plo, neigh, b1);
    stats_kernel<<<128, 128>>>(g1, be1);
    apply_bf16_kernel<<<(n4 + 255) / 256, 256>>>(n4);
    prepw_kernel<<<(896 * 128 + 255) / 256, 256>>>(W2, 896);
    conv_mma_kernel<128, 28><<<NBLK, 256, SMEM_TOTAL>>>(h1hi, h1lo, neigh, b2);
    stats_kernel<<<128, 128>>>(g2, be2);
    apply_final_kernel<<<(n4 + 255) / 256, 256>>>(out, n4);
}

// round 13
// speedup vs baseline: 1.8877x; 1.0150x over previous
#include <cuda_runtime.h>
#include <cuda_bf16.h>
#include <cstdint>

#define N_IN   163842
#define N_OUT  40962
#define NBLK   321          // ceil(40962/128)

// ======================= scratch (device globals) =========================
__device__ __align__(256) __nv_bfloat16 g_phi[N_OUT * 64];
__device__ __align__(256) __nv_bfloat16 g_plo[N_OUT * 64];
__device__ __align__(256) __nv_bfloat16 g_h1hi[N_OUT * 128];
__device__ __align__(256) __nv_bfloat16 g_h1lo[N_OUT * 128];
__device__ __align__(256) float g_raw[N_OUT * 128];
__device__ __align__(256) float g_part[2 * 128 * NBLK];
__device__ __align__(256) float g_coef[256];
// preconverted W^T as bf16 hi/lo, row-major [k][128]
__device__ __align__(256) __nv_bfloat16 g_Bhi[896 * 128];
__device__ __align__(256) __nv_bfloat16 g_Blo[896 * 128];

// ======================= asm helpers ======================================
__device__ __forceinline__ uint32_t smem_to_u32(const void* p) {
    uint32_t a;
    asm("{ .reg .u64 t; cvta.to.shared.u64 t, %1; cvt.u32.u64 %0, t; }" : "=r"(a) : "l"(p));
    return a;
}
#define CP16(dst, src) \
    asm volatile("cp.async.cg.shared.global [%0], [%1], 16;" :: "r"(dst), \
                 "l"(__cvta_generic_to_global(src)))
#define CP_COMMIT() asm volatile("cp.async.commit_group;" ::: "memory")
#define CP_WAIT1()  asm volatile("cp.async.wait_group 1;" ::: "memory")
#define CP_WAIT0()  asm volatile("cp.async.wait_group 0;" ::: "memory")

#define LDSM4(r, addr) \
    asm volatile("ldmatrix.sync.aligned.m8n8.x4.shared.b16 {%0,%1,%2,%3}, [%4];" \
        : "=r"((r)[0]), "=r"((r)[1]), "=r"((r)[2]), "=r"((r)[3]) : "r"(addr))
#define LDSM4T(r, addr) \
    asm volatile("ldmatrix.sync.aligned.m8n8.x4.trans.shared.b16 {%0,%1,%2,%3}, [%4];" \
        : "=r"((r)[0]), "=r"((r)[1]), "=r"((r)[2]), "=r"((r)[3]) : "r"(addr))
#define MMA_BF16(d, a, b) \
    asm volatile("mma.sync.aligned.m16n8k16.row.col.f32.bf16.bf16.f32 " \
        "{%0,%1,%2,%3}, {%4,%5,%6,%7}, {%8,%9}, {%0,%1,%2,%3};" \
        : "+f"((d)[0]), "+f"((d)[1]), "+f"((d)[2]), "+f"((d)[3]) \
        : "r"((a)[0]), "r"((a)[1]), "r"((a)[2]), "r"((a)[3]), "r"((b)[0]), "r"((b)[1]))

__device__ __forceinline__ void split_bf16(float v, __nv_bfloat16& hi, __nv_bfloat16& lo) {
    hi = __float2bfloat16(v);
    lo = __float2bfloat16(v - __bfloat162float(hi));
}

// smem: 3 stages of [Ah(128x80B) Al Bh(32x272B) Bl]; BK=32; 2 CTAs/SM.
// Reduction buffers ALIAS stage 0 (dead in epilogue; guarded by syncthreads).
#define A_STRIDE_B 80            // 32 bf16 data + 8 bf16 pad
#define B_STRIDE_B 272           // 128 bf16 data + 8 bf16 pad
#define OFF_AL 10240             // 128*80
#define OFF_BH 20480
#define OFF_BL 29184             // 20480 + 32*272
#define STAGE  37888
#define SMEM_TOTAL (3 * STAGE)   // 113664 -> 2 CTAs/SM

// ======================= pool: fp32 gather-mean -> bf16 hi/lo =============
__global__ void pool_kernel(const float* __restrict__ x, const int* __restrict__ po) {
    __shared__ float sh[8 * 448];
    int nb0 = blockIdx.x * 8;
    int tid = threadIdx.x;
    for (int e = tid; e < 8 * 448; e += 256) {
        int ln = e / 448;
        int q  = e - ln * 448;
        int node = nb0 + ln;
        if (node < N_OUT) {
            int r = q >> 6, c = q & 63;
            int srow = po[node * 7 + r];
            sh[e] = x[(size_t)srow * 64 + c];
        }
    }
    __syncthreads();
    for (int e = tid; e < 8 * 64; e += 256) {
        int ln = e >> 6, f = e & 63;
        int node = nb0 + ln;
        if (node < N_OUT) {
            const float* p = &sh[ln * 448 + f * 7];
            float s = (p[0] + p[1] + p[2] + p[3] + p[4] + p[5] + p[6]) * (1.0f / 7.0f);
            __nv_bfloat16 hi, lo; split_bf16(s, hi, lo);
            g_phi[node * 64 + f] = hi;
            g_plo[node * 64 + f] = lo;
        }
    }
}

// ======= prep W: (K,128) fp32 -> bf16 hi/lo, row-major [k][n] =============
__global__ void prepw_kernel(const float* __restrict__ W, int K) {
    int idx = blockIdx.x * 256 + threadIdx.x;
    if (idx >= K * 128) return;
    float v = W[idx];
    __nv_bfloat16 hi, lo; split_bf16(v, hi, lo);
    g_Bhi[idx] = hi;
    g_Blo[idx] = lo;
}

// ====== mma.sync gather-GEMM: (128 x 7C) @ (7C x 128) + bias + BN partials
// BK=32, 3 stages, single __syncthreads per chunk, 2 CTAs/SM.
template <int C, int NC>
__global__ void __launch_bounds__(256, 2) conv_mma_kernel(
    const __nv_bfloat16* __restrict__ shi,
    const __nv_bfloat16* __restrict__ slo,
    const int* __restrict__ neigh,
    const float* __restrict__ bias)
{
    extern __shared__ __align__(128) char sm[];
    const uint32_t sb = smem_to_u32(sm);
    const int t = threadIdx.x;
    const int w = t >> 5, l = t & 31;
    const int wm = w >> 1, wn = w & 1;
    const int bid = blockIdx.x, row0 = bid * 128;

    // gather indices for the row this thread stages (A: 2 threads per row)
    const int arow = t >> 1, ahalf = t & 1;
    int cn = row0 + arow; if (cn >= N_OUT) cn = N_OUT - 1;
    int nb[7];
#pragma unroll
    for (int j = 0; j < 7; j++) nb[j] = neigh[cn * 7 + j];

    const int brow = t >> 3, bseg = t & 7;    // B: 8 threads per row

    auto issue = [&](int c) {
        const int buf = c % 3;
        const uint32_t base = sb + buf * STAGE;
        const int j = (c * 32) / C, ch0 = (c * 32) % C + ahalf * 16;
        const __nv_bfloat16* srh = shi + (size_t)nb[j] * C + ch0;
        const __nv_bfloat16* srl = slo + (size_t)nb[j] * C + ch0;
        const uint32_t da  = base + arow * A_STRIDE_B + ahalf * 32;
        const uint32_t dal = base + OFF_AL + arow * A_STRIDE_B + ahalf * 32;
        CP16(da,       srh);
        CP16(da  + 16, srh + 8);
        CP16(dal,      srl);
        CP16(dal + 16, srl + 8);
        const __nv_bfloat16* sbh = g_Bhi + (size_t)(c * 32 + brow) * 128 + bseg * 16;
        const __nv_bfloat16* sbl = g_Blo + (size_t)(c * 32 + brow) * 128 + bseg * 16;
        const uint32_t db  = base + OFF_BH + brow * B_STRIDE_B + bseg * 32;
        const uint32_t dbl = base + OFF_BL + brow * B_STRIDE_B + bseg * 32;
        CP16(db,       sbh);
        CP16(db  + 16, sbh + 8);
        CP16(dbl,      sbl);
        CP16(dbl + 16, sbl + 8);
        CP_COMMIT();
    };

    float acc[64];
#pragma unroll
    for (int i = 0; i < 64; i++) acc[i] = 0.f;

    issue(0);
    issue(1);
    for (int c = 0; c < NC; c++) {
        if (c + 1 < NC) CP_WAIT1();
        else            CP_WAIT0();
        __syncthreads();
        // prefetch c+2 into buffer (c-1)%3 — all warps finished chunk c-1
        // (they passed this iteration's barrier), so the overwrite is safe.
        if (c + 2 < NC) issue(c + 2);
        const uint32_t base = sb + (c % 3) * STAGE;
        const uint32_t Ah = base, Al = base + OFF_AL;
        const uint32_t Bh = base + OFF_BH, Bl = base + OFF_BL;
#pragma unroll
        for (int ks = 0; ks < 2; ks++) {
            uint32_t ah[2][4], al[2][4];
#pragma unroll
            for (int mf = 0; mf < 2; mf++) {
                uint32_t ao = (uint32_t)(wm * 32 + mf * 16 + (l & 15)) * A_STRIDE_B
                              + ks * 32 + (l >> 4) * 16;
                LDSM4(ah[mf], Ah + ao);
                LDSM4(al[mf], Al + ao);
            }
#pragma unroll
            for (int g = 0; g < 4; g++) {
                uint32_t bh[4], bl[4];
                uint32_t bo = (uint32_t)(ks * 16 + (l & 15)) * B_STRIDE_B
                              + (wn * 64 + g * 16) * 2 + (l >> 4) * 16;
                LDSM4T(bh, Bh + bo);
                LDSM4T(bl, Bl + bo);
#pragma unroll
                for (int mf = 0; mf < 2; mf++) {
#pragma unroll
                    for (int nf2 = 0; nf2 < 2; nf2++) {
                        float* d = &acc[(mf * 8 + g * 2 + nf2) * 4];
                        MMA_BF16(d, ah[mf], &bh[nf2 * 2]);   // hi*hi
                        MMA_BF16(d, ah[mf], &bl[nf2 * 2]);   // hi*lo
                        MMA_BF16(d, al[mf], &bh[nf2 * 2]);   // lo*hi
                    }
                }
            }
        }
    }

    // ---------------- epilogue: bias, store, BN partials ------------------
    float ps[16], pq[16];
#pragma unroll
    for (int i = 0; i < 16; i++) { ps[i] = 0.f; pq[i] = 0.f; }

#pragma unroll
    for (int mf = 0; mf < 2; mf++) {
        int r1 = row0 + wm * 32 + mf * 16 + (l >> 2);
        int r2 = r1 + 8;
        bool v1 = r1 < N_OUT, v2 = r2 < N_OUT;
#pragma unroll
        for (int nf = 0; nf < 8; nf++) {
            int col = wn * 64 + nf * 8 + (l & 3) * 2;
            float b0 = __ldg(bias + col), b1 = __ldg(bias + col + 1);
            float* d = &acc[(mf * 8 + nf) * 4];
            float x0 = d[0] + b0, x1 = d[1] + b1;
            float x2 = d[2] + b0, x3 = d[3] + b1;
            if (v1) {
                float2 v; v.x = x0; v.y = x1;
                *(float2*)(g_raw + (size_t)r1 * 128 + col) = v;
                ps[nf * 2] += x0;     pq[nf * 2] += x0 * x0;
                ps[nf * 2 + 1] += x1; pq[nf * 2 + 1] += x1 * x1;
            }
            if (v2) {
                float2 v; v.x = x2; v.y = x3;
                *(float2*)(g_raw + (size_t)r2 * 128 + col) = v;
                ps[nf * 2] += x2;     pq[nf * 2] += x2 * x2;
                ps[nf * 2 + 1] += x3; pq[nf * 2 + 1] += x3 * x3;
            }
        }
    }
    // reduce over l>>2 (lanes differing in bits 2..4)
#pragma unroll
    for (int i = 0; i < 16; i++) {
#pragma unroll
        for (int o = 4; o <= 16; o <<= 1) {
            ps[i] += __shfl_xor_sync(0xffffffffu, ps[i], o);
            pq[i] += __shfl_xor_sync(0xffffffffu, pq[i], o);
        }
    }
    // rs/rq alias stage memory — barrier so no warp still reads the last
    // chunk's buffers before we overwrite them.
    __syncthreads();
    float* rs = (float*)(sm);
    float* rq = (float*)(sm + 4096);
    if (l < 4) {
#pragma unroll
        for (int nf = 0; nf < 8; nf++) {
            int col = wn * 64 + nf * 8 + l * 2;
            rs[w * 128 + col]     = ps[nf * 2];
            rs[w * 128 + col + 1] = ps[nf * 2 + 1];
            rq[w * 128 + col]     = pq[nf * 2];
            rq[w * 128 + col + 1] = pq[nf * 2 + 1];
        }
    }
    __syncthreads();
    if (t < 128) {
        int col = t, wnn = col >> 6;
        float S = 0.f, Q = 0.f;
#pragma unroll
        for (int wm2 = 0; wm2 < 4; wm2++) {
            S += rs[(wm2 * 2 + wnn) * 128 + col];
            Q += rq[(wm2 * 2 + wnn) * 128 + col];
        }
        g_part[(2 * col) * NBLK + bid] = S;
        g_part[(2 * col + 1) * NBLK + bid] = Q;
    }
}

// ------- per-channel BN coefficients: one block per channel ---------------
__global__ void __launch_bounds__(128) stats_kernel(const float* __restrict__ gamma,
                                                    const float* __restrict__ beta)
{
    __shared__ float shS[4], shQ[4];
    const int c = blockIdx.x;        // 128 blocks, one per channel
    const int t = threadIdx.x;       // 128 threads
    const float* pS = &g_part[(2 * c + 0) * NBLK];
    const float* pQ = &g_part[(2 * c + 1) * NBLK];
    float S = 0.f, Q = 0.f;
    for (int b = t; b < NBLK; b += 128) { S += pS[b]; Q += pQ[b]; }
#pragma unroll
    for (int o = 16; o > 0; o >>= 1) {
        S += __shfl_xor_sync(0xffffffffu, S, o);
        Q += __shfl_xor_sync(0xffffffffu, Q, o);
    }
    if ((t & 31) == 0) { shS[t >> 5] = S; shQ[t >> 5] = Q; }
    __syncthreads();
    if (t == 0) {
        S = shS[0] + shS[1] + shS[2] + shS[3];
        Q = shQ[0] + shQ[1] + shQ[2] + shQ[3];
        const float invM = 1.0f / (float)N_OUT;
        float m   = S * invM;
        float var = Q * invM - m * m;
        float istd = rsqrtf(var + 1e-5f);
        float a = gamma[c] * istd;
        g_coef[2 * c + 0] = a;
        g_coef[2 * c + 1] = beta[c] - m * a;
    }
}

// -------- BN apply + LeakyReLU -> bf16 hi/lo (intermediate layer) ---------
__global__ void apply_bf16_kernel(int n4)
{
    int i = blockIdx.x * blockDim.x + threadIdx.x;
    if (i >= n4) return;
    float4 v = ((const float4*)g_raw)[i];
    int c0 = (i * 4) & 127;
    float r[4] = {v.x, v.y, v.z, v.w};
    __nv_bfloat16 h[4], lo[4];
#pragma unroll
    for (int u = 0; u < 4; u++) {
        float a = __ldg(&g_coef[2 * (c0 + u) + 0]);
        float b = __ldg(&g_coef[2 * (c0 + u) + 1]);
        float y = fmaf(a, r[u], b);
        y = (y >= 0.f) ? y : 0.2f * y;
        split_bf16(y, h[u], lo[u]);
    }
    __nv_bfloat162* ph = (__nv_bfloat162*)g_h1hi;
    __nv_bfloat162* pl = (__nv_bfloat162*)g_h1lo;
    ph[i * 2 + 0] = __halves2bfloat162(h[0], h[1]);
    ph[i * 2 + 1] = __halves2bfloat162(h[2], h[3]);
    pl[i * 2 + 0] = __halves2bfloat162(lo[0], lo[1]);
    pl[i * 2 + 1] = __halves2bfloat162(lo[2], lo[3]);
}

// -------- BN apply + LeakyReLU -> fp32 (final output) ---------------------
__global__ void apply_final_kernel(float* __restrict__ out, int n4)
{
    int i = blockIdx.x * blockDim.x + threadIdx.x;
    if (i >= n4) return;
    float4 v = ((const float4*)g_raw)[i];
    int c0 = (i * 4) & 127;
    float r[4] = {v.x, v.y, v.z, v.w};
#pragma unroll
    for (int u = 0; u < 4; u++) {
        float a = __ldg(&g_coef[2 * (c0 + u) + 0]);
        float b = __ldg(&g_coef[2 * (c0 + u) + 1]);
        float y = fmaf(a, r[u], b);
        r[u] = (y >= 0.f) ? y : 0.2f * y;
    }
    v.x = r[0]; v.y = r[1]; v.z = r[2]; v.w = r[3];
    ((float4*)out)[i] = v;
}

// ---------------- launch ---------------------------------------------------
extern "C" void kernel_launch(void* const* d_in, const int* in_sizes, int n_in,
                              void* d_out, int out_size) {
    const float* x     = (const float*)d_in[0];
    const int*   neigh = (const int*)d_in[1];
    const int*   po    = (const int*)d_in[2];
    const float* W1    = (const float*)d_in[3];
    const float* b1    = (const float*)d_in[4];
    const float* g1    = (const float*)d_in[5];
    const float* be1   = (const float*)d_in[6];
    const float* W2    = (const float*)d_in[7];
    const float* b2    = (const float*)d_in[8];
    const float* g2    = (const float*)d_in[9];
    const float* be2   = (const float*)d_in[10];
    float* out = (float*)d_out;

    cudaFuncSetAttribute(conv_mma_kernel<64, 14>,
                         cudaFuncAttributeMaxDynamicSharedMemorySize, SMEM_TOTAL);
    cudaFuncSetAttribute(conv_mma_kernel<128, 28>,
                         cudaFuncAttributeMaxDynamicSharedMemorySize, SMEM_TOTAL);

    __nv_bfloat16 *phi, *plo, *h1hi, *h1lo;
    cudaGetSymbolAddress((void**)&phi,  g_phi);
    cudaGetSymbolAddress((void**)&plo,  g_plo);
    cudaGetSymbolAddress((void**)&h1hi, g_h1hi);
    cudaGetSymbolAddress((void**)&h1lo, g_h1lo);

    const int n4 = N_OUT * 32;            // N_OUT*128/4

    prepw_kernel<<<(448 * 128 + 255) / 256, 256>>>(W1, 448);
    pool_kernel<<<(N_OUT + 7) / 8, 256>>>(x, po);
    conv_mma_kernel<64, 14><<<NBLK, 256, SMEM_TOTAL>>>(phi, plo, neigh, b1);
    stats_kernel<<<128, 128>>>(g1, be1);
    apply_bf16_kernel<<<(n4 + 255) / 256, 256>>>(n4);
    prepw_kernel<<<(896 * 128 + 255) / 256, 256>>>(W2, 896);
    conv_mma_kernel<128, 28><<<NBLK, 256, SMEM_TOTAL>>>(h1hi, h1lo, neigh, b2);
    stats_kernel<<<128, 128>>>(g2, be2);
    apply_final_kernel<<<(n4 + 255) / 256, 256>>>(out, n4);
}